// round 8
// baseline (speedup 1.0000x reference)
#include <cuda_runtime.h>
#include <cuda_fp16.h>
#include <cstdint>

#define BSZ 256   // batch
#define SS  512   // seq
#define II  128   // in features
#define OO  128   // out features
#define LLG 11    // lags (MAX_LAG+1)
#define HH  16    // modulator hidden
#define HP  8     // half2 pairs (HH/2)
#define BPC 32    // batches per block chunk
#define BCH 8     // batch chunks (BPC*BCH == BSZ)
#define UF  4     // batches per inner iteration / staging group
#define NG  (BPC / UF)        // 8 groups
#define HB  (LLG * II)        // 1408 floats per staged batch
#define GB  (UF * HB)         // 5632 floats per group buffer
#define CHK (GB / 4)          // 1408 uint4 copies per group

__device__ float g_xm[BSZ * II];   // mean over S, [b][i]

__device__ __forceinline__ float tanh_fast(float x) {
    float y;
    asm("tanh.approx.f32 %0, %1;" : "=f"(y) : "f"(x));
    return y;
}
__device__ __forceinline__ __half2 tanh2_fast(__half2 x) {
    unsigned xi = *reinterpret_cast<unsigned*>(&x), yi;
    asm("tanh.approx.f16x2 %0, %1;" : "=r"(yi) : "r"(xi));
    return *reinterpret_cast<__half2*>(&yi);
}
// sigmoid(x) = 0.5*tanh(x/2) + 0.5   (single MUFU)
__device__ __forceinline__ float sigmoid_t(float x) {
    return fmaf(tanh_fast(0.5f * x), 0.5f, 0.5f);
}
__device__ __forceinline__ void cp16(uint32_t dst, const float* src) {
    asm volatile("cp.async.cg.shared.global [%0], [%1], 16;" :: "r"(dst), "l"(src));
}

// ---------------------------------------------------------------------------
// Kernel 1: xm[b][i] = mean_s x[b][s][i]; also zeroes out[b][:] for RED.ADD.
// ---------------------------------------------------------------------------
__global__ __launch_bounds__(512) void xm_kernel(const float* __restrict__ x,
                                                 float* __restrict__ out) {
    int b = blockIdx.x;
    int i = threadIdx.x & 127;
    int c = threadIdx.x >> 7;   // 0..3
    if (threadIdx.x < OO) out[(size_t)b * OO + threadIdx.x] = 0.0f;
    const float* p = x + (size_t)b * SS * II + (size_t)c * 128 * II + i;
    float s = 0.0f;
#pragma unroll 8
    for (int j = 0; j < 128; j++) s += p[(size_t)j * II];
    __shared__ float red[4][128];
    red[c][i] = s;
    __syncthreads();
    if (c == 0)
        g_xm[b * II + i] = (red[0][i] + red[1][i] + red[2][i] + red[3][i]) * (1.0f / SS);
}

// ---------------------------------------------------------------------------
// Per-(o,i) parameters in registers; MLP weights packed half2.
// ---------------------------------------------------------------------------
struct P {
    float   wl[LLG];
    float   C[5];
    __half2 W12[HP], B12[HP], W22[HP];
    float   b2v;
};

// sp points at this thread's column (offset by u*HB + i) inside the staged
// group buffer.  Staged row r (0..10) holds x[b][S-11+r]; lag l -> row 10-l.
__device__ __forceinline__ float triple_s(const float* __restrict__ sp,
                                          float xmv, const P& p) {
    float xla = 0.0f, xlb = 0.0f;
#pragma unroll
    for (int l = 0; l < LLG - 1; l += 2) {
        xla = fmaf(sp[(LLG - 1 - l) * II], p.wl[l],     xla);
        xlb = fmaf(sp[(LLG - 2 - l) * II], p.wl[l + 1], xlb);
    }
    xla = fmaf(sp[0], p.wl[LLG - 1], xla);
    float xl = xla + xlb;

    // spline lookup + lerp (s*4 < 4 -> knots 0..3)
    float s   = sigmoid_t(xl);
    float idx = s * 4.0f;
    int   k   = (int)idx;
    k = (k > 3) ? 3 : k;
    float w1f = idx - (float)k;
    float c0 = (k == 0) ? p.C[0] : (k == 1) ? p.C[1] : (k == 2) ? p.C[2] : p.C[3];
    float c1 = (k == 0) ? p.C[1] : (k == 1) ? p.C[2] : (k == 2) ? p.C[3] : p.C[4];
    float y  = fmaf(c1 - c0, w1f, c0);

    // modulator MLP in f16x2: 8 HFMA2 + 8 tanh.f16x2 + 8 HFMA2
    __half2 xm2 = __float2half2_rn(xmv);
    __half2 a0 = __float2half2_rn(0.0f), a1 = a0;
#pragma unroll
    for (int h = 0; h < HP; h += 2) {
        __half2 t0 = tanh2_fast(__hfma2(xm2, p.W12[h],     p.B12[h]));
        __half2 t1 = tanh2_fast(__hfma2(xm2, p.W12[h + 1], p.B12[h + 1]));
        a0 = __hfma2(t0, p.W22[h],     a0);
        a1 = __hfma2(t1, p.W22[h + 1], a1);
    }
    float2 f0 = __half22float2(a0);
    float2 f1 = __half22float2(a1);
    float acc = p.b2v + (f0.x + f0.y) + (f1.x + f1.y);
    float alpha = sigmoid_t(acc);
    return y * alpha;
}

// Cooperative copy of one group (UF batches x last-11 rows, contiguous per
// batch) into smem via cp.async.
__device__ __forceinline__ void load_group(const float* __restrict__ x,
                                           int bstart, uint32_t sdst, int tid) {
#pragma unroll
    for (int c = tid; c < CHK; c += 256) {
        int u = c / (HB / 4);          // HB/4 = 352 uint4 per batch
        int j = c - u * (HB / 4);
        const float* src = x + ((size_t)(bstart + u) * SS + (SS - LLG)) * II + j * 4;
        cp16(sdst + c * 16, src);
    }
}

// ---------------------------------------------------------------------------
// Kernel 2: main.  grid=(64, 8), block=256 = 2 o-rows x 128 i, occ 2.
// Double-buffered cp.async staging of hist; xm register-prefetched one group
// ahead; UF=4 ILP; warp shfl reduce + RED.E.ADD.
// ---------------------------------------------------------------------------
__global__ __launch_bounds__(256, 2) void main_kernel(
    const float* __restrict__ x,
    const float* __restrict__ coeffs,
    const float* __restrict__ lag_logits,
    const float* __restrict__ mw1,
    const float* __restrict__ mb1,
    const float* __restrict__ mw2,
    const float* __restrict__ mb2,
    const float* __restrict__ edge,
    float* __restrict__ out)
{
    __shared__ float sh[2][GB];        // 45056 bytes

    int tid = threadIdx.x;
    int i  = tid & 127;
    int ol = tid >> 7;                 // 0 or 1
    int o  = blockIdx.x * 2 + ol;
    int oi = o * II + i;
    int b0 = blockIdx.y * BPC;

    uint32_t sbase = (uint32_t)__cvta_generic_to_shared(&sh[0][0]);

    // kick off group 0 staging before the (long) parameter prologue
    load_group(x, b0, sbase, tid);
    asm volatile("cp.async.commit_group;");

    P p;
    // softmax over lag logits (amortized over BPC batches)
    float m = -1e30f;
#pragma unroll
    for (int l = 0; l < LLG; l++) { p.wl[l] = lag_logits[oi * LLG + l]; m = fmaxf(m, p.wl[l]); }
    float sum = 0.0f;
#pragma unroll
    for (int l = 0; l < LLG; l++) { p.wl[l] = __expf(p.wl[l] - m); sum += p.wl[l]; }
    float inv = __fdividef(1.0f, sum);
#pragma unroll
    for (int l = 0; l < LLG; l++) p.wl[l] *= inv;

    // edge mask folded into coefficients; s*4 < 4 => only coeffs[0..4]
    float mask = (edge[oi] > 0.0f) ? 1.0f : 0.0f;
#pragma unroll
    for (int j = 0; j < 5; j++) p.C[j] = coeffs[oi * 8 + j] * mask;

#pragma unroll
    for (int h = 0; h < HP; h++) {
        p.W12[h] = __floats2half2_rn(mw1[oi * HH + 2 * h], mw1[oi * HH + 2 * h + 1]);
        p.B12[h] = __floats2half2_rn(mb1[oi * HH + 2 * h], mb1[oi * HH + 2 * h + 1]);
        p.W22[h] = __floats2half2_rn(mw2[oi * HH + 2 * h], mw2[oi * HH + 2 * h + 1]);
    }
    p.b2v = mb2[oi];

    const float* xmp = g_xm + (size_t)b0 * II + i;
    float* outp = out + (size_t)b0 * OO + o;

    // xm for group 0
    float xmc[UF];
#pragma unroll
    for (int u = 0; u < UF; u++) xmc[u] = xmp[u * II];

    for (int g = 0; g < NG; g++) {
        float xmn[UF];
        if (g + 1 < NG) {
            // issue next group's staging + xm prefetch, then wait for current
            load_group(x, b0 + (g + 1) * UF, sbase + (((g + 1) & 1) * GB) * 4, tid);
            asm volatile("cp.async.commit_group;");
#pragma unroll
            for (int u = 0; u < UF; u++) xmn[u] = xmp[((g + 1) * UF + u) * II];
            asm volatile("cp.async.wait_group 1;");
        } else {
#pragma unroll
            for (int u = 0; u < UF; u++) xmn[u] = 0.0f;
            asm volatile("cp.async.wait_group 0;");
        }
        __syncthreads();

        const float* sp = &sh[g & 1][0] + i;
        float v[UF];
#pragma unroll
        for (int u = 0; u < UF; u++)
            v[u] = triple_s(sp + u * HB, xmc[u], p);

        // warp-level i-reduction, UF independent trees interleaved
#pragma unroll
        for (int off = 16; off; off >>= 1)
#pragma unroll
            for (int u = 0; u < UF; u++)
                v[u] += __shfl_xor_sync(0xffffffffu, v[u], off);

        if ((tid & 31) == 0) {
            int bb = g * UF;
#pragma unroll
            for (int u = 0; u < UF; u++)
                atomicAdd(outp + (size_t)(bb + u) * OO, v[u]);   // -> RED.E.ADD
        }
        __syncthreads();   // protect buffer (g&1) before it is re-staged

#pragma unroll
        for (int u = 0; u < UF; u++) xmc[u] = xmn[u];
    }
}

extern "C" void kernel_launch(void* const* d_in, const int* in_sizes, int n_in,
                              void* d_out, int out_size) {
    const float* x      = (const float*)d_in[0];
    const float* coeffs = (const float*)d_in[1];
    const float* lag    = (const float*)d_in[2];
    const float* mw1    = (const float*)d_in[3];
    const float* mb1    = (const float*)d_in[4];
    const float* mw2    = (const float*)d_in[5];
    const float* mb2    = (const float*)d_in[6];
    const float* edge   = (const float*)d_in[7];
    float* out = (float*)d_out;

    xm_kernel<<<BSZ, 512>>>(x, out);
    dim3 grid(OO / 2, BCH);
    main_kernel<<<grid, 256>>>(x, coeffs, lag, mw1, mb1, mw2, mb2, edge, out);
}